// round 3
// baseline (speedup 1.0000x reference)
#include <cuda_runtime.h>
#include <cstdint>

#define GRIDL 256
#define CELLS (130 * 256 * 256)   // coords reach 129 = 127 + tap 2
#define NMAX  262144

// Dense voxel grid: head[cell] = point_index+1 (0 = empty), chained via g_next
__device__ int g_head[CELLS];
__device__ int g_next[NMAX];

__global__ void init_head() {
    int stride = gridDim.x * blockDim.x;
    for (int i = blockIdx.x * blockDim.x + threadIdx.x; i < CELLS; i += stride)
        g_head[i] = 0;
}

__global__ void build_chains(const int* __restrict__ in_pos, int N) {
    int n = blockIdx.x * blockDim.x + threadIdx.x;
    if (n >= N) return;
    int x = in_pos[3 * n + 0];
    int y = in_pos[3 * n + 1];
    int z = in_pos[3 * n + 2];
    int lid = (x * GRIDL + y) * GRIDL + z;
    int old = atomicExch(&g_head[lid], n + 1);
    g_next[n] = old;
}

// Shared layout per CTA:
//   WT: one tap, transposed+padded: WT[f*36 + c] = W[k][c][f]  (1152 floats)
//   acc: 8 warps x 64 rows x 32 feats (16384 floats)
#define WT_STRIDE 36
#define SM_WT     (32 * WT_STRIDE)            // 1152 floats
#define ROWS_PER_WARP 64
#define WARPS 8
#define ROWS_PER_CTA (WARPS * ROWS_PER_WARP)  // 512
#define SM_ACC (ROWS_PER_CTA * 32)            // 16384 floats
#define SMEM_BYTES ((SM_WT + SM_ACC) * 4)     // 70144 bytes

__device__ __forceinline__ unsigned long long pack2(float lo, float hi) {
    float2 t = make_float2(lo, hi);
    return *reinterpret_cast<unsigned long long*>(&t);
}

__global__ __launch_bounds__(256, 3)
void gather_conv(const float* __restrict__ feat,
                 const int*   __restrict__ out_pos,
                 const float* __restrict__ W,
                 float*       __restrict__ out,
                 int M) {
    extern __shared__ float sm[];
    float* WT  = sm;
    float* acc = sm + SM_WT;

    int tid  = threadIdx.x;
    int warp = tid >> 5;
    int lane = tid & 31;

    float* accG = acc + warp * (ROWS_PER_WARP * 32);   // [64 rows][32 f]

    // zero this warp's accumulators (lane = feature column)
    #pragma unroll
    for (int r = 0; r < ROWS_PER_WARP; r++) accG[r * 32 + lane] = 0.0f;

    int rowBase = blockIdx.x * ROWS_PER_CTA + warp * ROWS_PER_WARP;
    int row0 = rowBase + lane;
    int row1 = row0 + 32;
    bool v0 = row0 < M;
    bool v1 = row1 < M;
    int lid0 = 0, lid1 = 0;
    if (v0) {
        int x = out_pos[3 * row0 + 0], y = out_pos[3 * row0 + 1], z = out_pos[3 * row0 + 2];
        lid0 = (x * GRIDL + y) * GRIDL + z;
    }
    if (v1) {
        int x = out_pos[3 * row1 + 0], y = out_pos[3 * row1 + 1], z = out_pos[3 * row1 + 2];
        lid1 = (x * GRIDL + y) * GRIDL + z;
    }

    const ulonglong2* featv = (const ulonglong2*)feat;   // 8 x 16B per point

    for (int k = 0; k < 27; k++) {
        __syncthreads();
        // stage tap k of W, transposed: WT[f*36+c] = W[k*1024 + c*32 + f]
        #pragma unroll
        for (int i = tid; i < 1024; i += 256) {
            int c = i >> 5, f = i & 31;
            WT[f * WT_STRIDE + c] = W[k * 1024 + i];
        }
        __syncthreads();

        int di = k / 9;
        int rem = k - di * 9;
        int dj = rem / 3;
        int dk = rem - dj * 3;
        int off = di * (GRIDL * GRIDL) + dj * GRIDL + dk;

        int h0 = v0 ? __ldg(&g_head[lid0 + off]) : 0;
        int h1 = v1 ? __ldg(&g_head[lid1 + off]) : 0;
        unsigned m0 = __ballot_sync(0xffffffffu, h0 != 0);
        unsigned m1 = __ballot_sync(0xffffffffu, h1 != 0);
        if (!(m0 | m1)) continue;

        // hoist tap-k weight column for this lane's feature into f32x2 registers
        unsigned long long w[16];
        const float4* wrow = (const float4*)(WT + lane * WT_STRIDE);
        #pragma unroll
        for (int i = 0; i < 8; i++) {
            float4 t = wrow[i];
            w[2 * i + 0] = pack2(t.x, t.y);
            w[2 * i + 1] = pack2(t.z, t.w);
        }

        #pragma unroll
        for (int half = 0; half < 2; half++) {
            unsigned mask = half ? m1 : m0;
            int head = half ? h1 : h0;
            float* accH = accG + half * (32 * 32);
            while (mask) {
                int r = __ffs(mask) - 1;
                mask &= mask - 1;
                int p = __shfl_sync(0xffffffffu, head, r);
                unsigned long long a2 = pack2(accH[r * 32 + lane], 0.0f);
                do {
                    int n = p - 1;
                    const ulonglong2* f2 = featv + (size_t)n * 8;   // 32 floats = 8 x ulonglong2
                    #pragma unroll
                    for (int i = 0; i < 8; i++) {
                        ulonglong2 v = __ldg(f2 + i);
                        asm("fma.rn.f32x2 %0, %1, %2, %0;" : "+l"(a2) : "l"(v.x), "l"(w[2 * i + 0]));
                        asm("fma.rn.f32x2 %0, %1, %2, %0;" : "+l"(a2) : "l"(v.y), "l"(w[2 * i + 1]));
                    }
                    p = __ldg(&g_next[n]);
                } while (p);
                float2 rr = *reinterpret_cast<float2*>(&a2);
                accH[r * 32 + lane] = rr.x + rr.y;
            }
        }
    }

    // write results (coalesced: 128B per row)
    #pragma unroll
    for (int r = 0; r < ROWS_PER_WARP; r++) {
        int row = rowBase + r;
        if (row < M) out[row * 32 + lane] = accG[r * 32 + lane];
    }
}

extern "C" void kernel_launch(void* const* d_in, const int* in_sizes, int n_in,
                              void* d_out, int out_size) {
    const float* feat    = (const float*)d_in[0];
    const int*   in_pos  = (const int*)d_in[1];
    const int*   out_pos = (const int*)d_in[2];
    const float* W       = (const float*)d_in[3];
    float* out = (float*)d_out;

    int N = in_sizes[0] / 32;
    int M = in_sizes[2] / 3;

    cudaFuncSetAttribute(gather_conv, cudaFuncAttributeMaxDynamicSharedMemorySize, SMEM_BYTES);

    init_head<<<4096, 256>>>();
    build_chains<<<(N + 255) / 256, 256>>>(in_pos, N);
    gather_conv<<<(M + ROWS_PER_CTA - 1) / ROWS_PER_CTA, 256, SMEM_BYTES>>>(feat, out_pos, W, out, M);
}